// round 7
// baseline (speedup 1.0000x reference)
#include <cuda_runtime.h>
#include <cuda_fp16.h>
#include <math.h>
#include <stdint.h>

#define NBATCH 192
#define NTOK   256
#define CDIM   256
#define NH     8
#define HD     32
#define QKVD   768   // 3*C

#define LOG2E 1.4426950408889634f

// ---------------- scratch (static __device__, no runtime alloc) ----------------
__device__ __half g_qkv [NBATCH * NTOK * QKVD];   // fp16, Q pre-scaled by scale*log2e
__device__ float  g_bias[NH * NTOK * NTOK];       // (bias - 8) * log2e
__device__ __half g_att [NBATCH * NTOK * CDIM];   // attention out fp16
__device__ __half g_xh  [NBATCH * NTOK * CDIM];   // x in fp16
__device__ __half g_wh  [QKVD * CDIM + CDIM * CDIM]; // fp16 qkv_w | proj_w

// ---------------- helpers ----------------
__device__ __forceinline__ void cp16(void* smemp, const void* g) {
    uint32_t s = (uint32_t)__cvta_generic_to_shared(smemp);
    asm volatile("cp.async.cg.shared.global [%0], [%1], 16;" :: "r"(s), "l"(g));
}
__device__ __forceinline__ void cp_commit() { asm volatile("cp.async.commit_group;"); }
__device__ __forceinline__ void mma_f16(float c[4], const uint32_t a[4], const uint32_t b[2]) {
    asm volatile(
        "mma.sync.aligned.m16n8k16.row.col.f32.f16.f16.f32 "
        "{%0,%1,%2,%3}, {%4,%5,%6,%7}, {%8,%9}, {%0,%1,%2,%3};"
        : "+f"(c[0]), "+f"(c[1]), "+f"(c[2]), "+f"(c[3])
        : "r"(a[0]), "r"(a[1]), "r"(a[2]), "r"(a[3]), "r"(b[0]), "r"(b[1]));
}
__device__ __forceinline__ uint32_t ldu32(const __half* p) {
    return *(const uint32_t*)p;
}
__device__ __forceinline__ float ex2(float x) {
    float r; asm("ex2.approx.f32 %0, %1;" : "=f"(r) : "f"(x)); return r;
}

// ---------------- prep: fp32 -> fp16 ----------------
__global__ void tohalf_kernel(const float2* __restrict__ in, __half2* __restrict__ out, int n2) {
    int i = blockIdx.x * blockDim.x + threadIdx.x;
    if (i >= n2) return;
    float2 v = in[i];
    out[i] = __floats2half2_rn(v.x, v.y);
}

// ---------------- rel-pos bias gather: (bias - 8) * log2e ----------------
__global__ void bias_kernel(const float* __restrict__ table,
                            const int*   __restrict__ ridx) {
    int nm = blockIdx.x * blockDim.x + threadIdx.x;
    if (nm >= NTOK * NTOK) return;
    int ri = ridx[nm];
    #pragma unroll
    for (int h = 0; h < NH; h++)
        g_bias[h * NTOK * NTOK + nm] = (table[ri * NH + h] - 8.0f) * LOG2E;
}

// ---------------- fp16 NT GEMM (2-stage cp.async): C = A*B^T + bias ----------
// A: (M,K) half, B: (N,K) half. QKV_MODE: half output, Q cols pre-scaled.
#define GSSH 40                 // smem row stride in halfs (80B rows, CF LDS.32)
#define GSTH (128 * GSSH)
template<bool QKV_MODE>
__global__ __launch_bounds__(256, 2)
void gemm_f16(const __half* __restrict__ A, const __half* __restrict__ B,
              const float* __restrict__ bias, void* __restrict__ Cv,
              int M, int N, int K)
{
    extern __shared__ __half smh[];
    __half* As = smh;                 // 2 stages
    __half* Bs = smh + 2 * GSTH;

    const int tid  = threadIdx.x;
    const int warp = tid >> 5, lane = tid & 31;
    const int qg   = lane >> 2, tg = lane & 3;
    const int wm   = (warp >> 2) * 64;
    const int wn   = (warp & 3) * 32;
    const int row0 = blockIdx.y * 128, col0 = blockIdx.x * 128;

    float c[4][4][4];
    #pragma unroll
    for (int i = 0; i < 4; i++)
        #pragma unroll
        for (int j = 0; j < 4; j++)
            #pragma unroll
            for (int t = 0; t < 4; t++) c[i][j][t] = 0.0f;

    const int KT = K / 32;

    auto load_stage = [&](int stage, int k0) {
        #pragma unroll
        for (int i = 0; i < 2; i++) {
            int id = tid + i * 256;        // 512 chunks per matrix
            int r = id >> 2, c8 = (id & 3) * 8;
            cp16(As + stage * GSTH + r * GSSH + c8,
                 A + (size_t)(row0 + r) * K + k0 + c8);
            cp16(Bs + stage * GSTH + r * GSSH + c8,
                 B + (size_t)(col0 + r) * K + k0 + c8);
        }
        cp_commit();
    };

    load_stage(0, 0);

    for (int kt = 0; kt < KT; kt++) {
        if (kt + 1 < KT) {
            load_stage((kt + 1) & 1, (kt + 1) * 32);
            asm volatile("cp.async.wait_group 1;");
        } else {
            asm volatile("cp.async.wait_group 0;");
        }
        __syncthreads();

        const __half* Asb = As + (kt & 1) * GSTH;
        const __half* Bsb = Bs + (kt & 1) * GSTH;

        #pragma unroll
        for (int ks = 0; ks < 2; ks++) {           // two k16 steps per 32-k tile
            int kk = ks * 16 + 2 * tg;
            uint32_t af[4][4], bf[4][2];
            #pragma unroll
            for (int i = 0; i < 4; i++) {
                const __half* p = Asb + (wm + i * 16 + qg) * GSSH + kk;
                af[i][0] = ldu32(p);
                af[i][1] = ldu32(p + 8 * GSSH);
                af[i][2] = ldu32(p + 8);
                af[i][3] = ldu32(p + 8 * GSSH + 8);
            }
            #pragma unroll
            for (int j = 0; j < 4; j++) {
                const __half* p = Bsb + (wn + j * 8 + qg) * GSSH + kk;
                bf[j][0] = ldu32(p);
                bf[j][1] = ldu32(p + 8);
            }
            #pragma unroll
            for (int i = 0; i < 4; i++)
                #pragma unroll
                for (int j = 0; j < 4; j++)
                    mma_f16(c[i][j], af[i], bf[j]);
        }
        __syncthreads();
    }

    const float qscale = (float)(0.17677669529663687 * 1.4426950408889634);
    #pragma unroll
    for (int i = 0; i < 4; i++) {
        int row = row0 + wm + i * 16 + qg;
        #pragma unroll
        for (int j = 0; j < 4; j++) {
            int col = col0 + wn + j * 8 + 2 * tg;
            float b0 = bias[col], b1 = bias[col + 1];
            float v00 = c[i][j][0] + b0, v01 = c[i][j][1] + b1;
            float v10 = c[i][j][2] + b0, v11 = c[i][j][3] + b1;
            if (QKV_MODE) {
                if (col < 256) { v00 *= qscale; v01 *= qscale; v10 *= qscale; v11 *= qscale; }
                __half* C = (__half*)Cv;
                *(__half2*)&C[(size_t)row * N + col]       = __floats2half2_rn(v00, v01);
                *(__half2*)&C[(size_t)(row + 8) * N + col] = __floats2half2_rn(v10, v11);
            } else {
                float* C = (float*)Cv;
                *(float2*)&C[(size_t)row * N + col]       = make_float2(v00, v01);
                *(float2*)&C[(size_t)(row + 8) * N + col] = make_float2(v10, v11);
            }
        }
    }
}

// ---------------- fp16 flash attention, fixed-max exp2 softmax ----------------
// CTA per (b,h), 8 warps x 32 rows, 32-key blocks. V transposed in smem.
#define KSH 40     // K row stride (halfs)
#define VTS 264    // V^T row stride (halfs): 32 dims x 264
#define PSH 40     // P tile row stride (halfs)
__global__ __launch_bounds__(256, 2)
void attn_f16(const float* __restrict__ mask)
{
    extern __shared__ __half smh[];
    __half* Ks = smh;                        // 256*40
    __half* Vt = Ks + 256 * KSH;             // 32*264
    __half* Ps = Vt + 32 * VTS;              // 8 warps * 32*40

    const int bh = blockIdx.x, b = bh >> 3, h = bh & 7;
    const int tid = threadIdx.x, warp = tid >> 5, lane = tid & 31;
    const int qg = lane >> 2, tg = lane & 3;

    const __half* base = g_qkv + (size_t)b * NTOK * QKVD + h * 32;

    // stage K via cp.async (256 rows x 64B)
    #pragma unroll
    for (int i = 0; i < 4; i++) {
        int id = tid + i * 256;
        int m = id >> 2, c8 = (id & 3) * 8;
        cp16(Ks + m * KSH + c8, base + m * QKVD + 256 + c8);
    }
    cp_commit();

    // stage V transposed: thread tid = key m, 32 dims
    {
        const uint4* vsrc = (const uint4*)(base + (size_t)tid * QKVD + 512);
        uint4 vv[4];
        #pragma unroll
        for (int i = 0; i < 4; i++) vv[i] = vsrc[i];
        const __half* vh = (const __half*)vv;
        #pragma unroll
        for (int d = 0; d < 32; d++)
            Vt[d * VTS + tid] = vh[d];
    }

    const int wm = warp * 32;
    __half* Pw = Ps + warp * 32 * PSH;
    const float* bias_h = g_bias + (size_t)h * NTOK * NTOK;
    const float* mask_w = mask + (size_t)(b & 63) * NTOK * NTOK;

    // persistent Q fragments from global (pre-scaled fp16)
    uint32_t qf[2][2][4];
    #pragma unroll
    for (int i = 0; i < 2; i++)
        #pragma unroll
        for (int ks = 0; ks < 2; ks++) {
            const __half* p = base + (size_t)(wm + 16 * i + qg) * QKVD + 16 * ks + 2 * tg;
            qf[i][ks][0] = ldu32(p);
            qf[i][ks][1] = ldu32(p + 8 * QKVD);
            qf[i][ks][2] = ldu32(p + 8);
            qf[i][ks][3] = ldu32(p + 8 * QKVD + 8);
        }

    float O[2][4][4];
    #pragma unroll
    for (int i = 0; i < 2; i++)
        #pragma unroll
        for (int j = 0; j < 4; j++)
            #pragma unroll
            for (int t = 0; t < 4; t++) O[i][j][t] = 0.0f;
    float lrun[4] = {0.f, 0.f, 0.f, 0.f};

    asm volatile("cp.async.wait_group 0;");
    __syncthreads();

    #pragma unroll 1
    for (int nb = 0; nb < 8; nb++) {
        const int n0 = nb * 32;

        // ---- S init: (bias-8)*log2e + mask*log2e
        float S[2][4][4];
        #pragma unroll
        for (int i = 0; i < 2; i++) {
            int row = wm + 16 * i + qg;
            #pragma unroll
            for (int j = 0; j < 4; j++) {
                int col = n0 + 8 * j + 2 * tg;
                float2 b0 = *(const float2*)(bias_h + (size_t)row * NTOK + col);
                float2 m0 = *(const float2*)(mask_w + (size_t)row * NTOK + col);
                float2 b1 = *(const float2*)(bias_h + (size_t)(row + 8) * NTOK + col);
                float2 m1 = *(const float2*)(mask_w + (size_t)(row + 8) * NTOK + col);
                S[i][j][0] = fmaf(m0.x, LOG2E, b0.x);
                S[i][j][1] = fmaf(m0.y, LOG2E, b0.y);
                S[i][j][2] = fmaf(m1.x, LOG2E, b1.x);
                S[i][j][3] = fmaf(m1.y, LOG2E, b1.y);
            }
        }

        // ---- S += Q K^T (32 keys, 2 k16 steps over dims)
        #pragma unroll
        for (int ks = 0; ks < 2; ks++) {
            #pragma unroll
            for (int j = 0; j < 4; j++) {
                const __half* p = Ks + (n0 + 8 * j + qg) * KSH + 16 * ks + 2 * tg;
                uint32_t bf[2] = { ldu32(p), ldu32(p + 8) };
                mma_f16(S[0][j], qf[0][ks], bf);
                mma_f16(S[1][j], qf[1][ks], bf);
            }
        }

        // ---- fixed-max softmax: p = 2^S (S <= ~-1 by construction)
        #pragma unroll
        for (int i = 0; i < 2; i++)
            #pragma unroll
            for (int e = 0; e < 2; e++) {
                const int r = 2 * i + e;
                float psum = 0.0f;
                __half* prow = Pw + (16 * i + 8 * e + qg) * PSH + 2 * tg;
                #pragma unroll
                for (int j = 0; j < 4; j++) {
                    float p0 = ex2(S[i][j][2 * e]);
                    float p1 = ex2(S[i][j][2 * e + 1]);
                    psum += p0 + p1;
                    *(__half2*)(prow + 8 * j) = __floats2half2_rn(p0, p1);
                }
                psum += __shfl_xor_sync(0xffffffffu, psum, 1);
                psum += __shfl_xor_sync(0xffffffffu, psum, 2);
                lrun[r] += psum;
            }
        __syncwarp();

        // ---- O += P V (32 keys = 2 k16 steps)
        #pragma unroll
        for (int ks = 0; ks < 2; ks++) {
            uint32_t af[2][4];
            #pragma unroll
            for (int i = 0; i < 2; i++) {
                const __half* p = Pw + (16 * i + qg) * PSH + 16 * ks + 2 * tg;
                af[i][0] = ldu32(p);
                af[i][1] = ldu32(p + 8 * PSH);
                af[i][2] = ldu32(p + 8);
                af[i][3] = ldu32(p + 8 * PSH + 8);
            }
            #pragma unroll
            for (int j = 0; j < 4; j++) {
                const __half* p = Vt + (8 * j + qg) * VTS + n0 + 16 * ks + 2 * tg;
                uint32_t bf[2] = { ldu32(p), ldu32(p + 8) };
                mma_f16(O[0][j], af[0], bf);
                mma_f16(O[1][j], af[1], bf);
            }
        }
        __syncwarp();
    }

    float inv[4];
    #pragma unroll
    for (int r = 0; r < 4; r++) inv[r] = 1.0f / lrun[r];

    #pragma unroll
    for (int i = 0; i < 2; i++) {
        int row = wm + 16 * i + qg;
        #pragma unroll
        for (int j = 0; j < 4; j++) {
            int col = h * 32 + 8 * j + 2 * tg;
            *(__half2*)&g_att[((size_t)b * NTOK + row) * CDIM + col] =
                __floats2half2_rn(O[i][j][0] * inv[2 * i], O[i][j][1] * inv[2 * i]);
            *(__half2*)&g_att[((size_t)b * NTOK + row + 8) * CDIM + col] =
                __floats2half2_rn(O[i][j][2] * inv[2 * i + 1], O[i][j][3] * inv[2 * i + 1]);
        }
    }
}

// --------------------------------------------------------------------------
extern "C" void kernel_launch(void* const* d_in, const int* in_sizes, int n_in,
                              void* d_out, int out_size)
{
    const float* x      = (const float*)d_in[0];
    const float* mask   = (const float*)d_in[1];
    const float* qkv_w  = (const float*)d_in[2];
    const float* qkv_b  = (const float*)d_in[3];
    const float* proj_w = (const float*)d_in[4];
    const float* proj_b = (const float*)d_in[5];
    const float* table  = (const float*)d_in[6];
    const int*   ridx   = (const int*)d_in[7];
    float* out = (float*)d_out;

    __half *qkv_ptr, *att_ptr, *xh_ptr, *wh_ptr;
    cudaGetSymbolAddress((void**)&qkv_ptr, g_qkv);
    cudaGetSymbolAddress((void**)&att_ptr, g_att);
    cudaGetSymbolAddress((void**)&xh_ptr,  g_xh);
    cudaGetSymbolAddress((void**)&wh_ptr,  g_wh);
    __half* qkvw_h = wh_ptr;
    __half* projw_h = wh_ptr + QKVD * CDIM;

    const int gemm_smem = 2 * 2 * GSTH * 2;                              // 40960 B
    const int attn_smem = (256 * KSH + 32 * VTS + 8 * 32 * PSH) * 2;     // 57856 B
    cudaFuncSetAttribute((const void*)gemm_f16<true>,
                         cudaFuncAttributeMaxDynamicSharedMemorySize, gemm_smem);
    cudaFuncSetAttribute((const void*)gemm_f16<false>,
                         cudaFuncAttributeMaxDynamicSharedMemorySize, gemm_smem);
    cudaFuncSetAttribute((const void*)attn_f16,
                         cudaFuncAttributeMaxDynamicSharedMemorySize, attn_smem);

    // 0) prep: fp32 -> fp16 conversions
    tohalf_kernel<<<(NBATCH * NTOK * CDIM / 2 + 255) / 256, 256>>>(
        (const float2*)x, (__half2*)xh_ptr, NBATCH * NTOK * CDIM / 2);
    tohalf_kernel<<<(QKVD * CDIM / 2 + 255) / 256, 256>>>(
        (const float2*)qkv_w, (__half2*)qkvw_h, QKVD * CDIM / 2);
    tohalf_kernel<<<(CDIM * CDIM / 2 + 255) / 256, 256>>>(
        (const float2*)proj_w, (__half2*)projw_h, CDIM * CDIM / 2);

    // 1) rel-pos bias gather (pre-shifted, log2e-scaled)
    bias_kernel<<<(NTOK * NTOK + 255) / 256, 256>>>(table, ridx);

    // 2) QKV projection -> fp16 (Q pre-scaled by scale*log2e)
    gemm_f16<true><<<dim3(QKVD / 128, (NBATCH * NTOK) / 128), 256, gemm_smem>>>(
        xh_ptr, qkvw_h, qkv_b, qkv_ptr, NBATCH * NTOK, QKVD, CDIM);

    // 3) window attention
    attn_f16<<<NBATCH * NH, 256, attn_smem>>>(mask);

    // 4) output projection -> fp32 d_out
    gemm_f16<false><<<dim3(CDIM / 128, (NBATCH * NTOK) / 128), 256, gemm_smem>>>(
        att_ptr, projw_h, proj_b, out, NBATCH * NTOK, CDIM, CDIM);
}

// round 8
// speedup vs baseline: 1.7501x; 1.7501x over previous
#include <cuda_runtime.h>
#include <cuda_fp16.h>
#include <math.h>
#include <stdint.h>

#define NBATCH 192
#define NTOK   256
#define CDIM   256
#define NH     8
#define HD     32
#define QKVD   768   // 3*C

#define LOG2E 1.4426950408889634f

// ---------------- scratch (static __device__, no runtime alloc) ----------------
__device__ __half g_qkv [NBATCH * NTOK * QKVD];   // fp16, Q pre-scaled by scale*log2e
__device__ float  g_bias[NH * NTOK * NTOK];       // (bias - 8) * log2e
__device__ __half g_att [NBATCH * NTOK * CDIM];   // attention out fp16
__device__ __half g_xh  [NBATCH * NTOK * CDIM];   // x in fp16
__device__ __half g_wh  [QKVD * CDIM + CDIM * CDIM]; // fp16 qkv_w | proj_w

// ---------------- helpers ----------------
__device__ __forceinline__ void cp16(uint32_t saddr, const void* g) {
    asm volatile("cp.async.cg.shared.global [%0], [%1], 16;" :: "r"(saddr), "l"(g));
}
__device__ __forceinline__ void cp_commit() { asm volatile("cp.async.commit_group;"); }
__device__ __forceinline__ void mma_f16(float c[4], const uint32_t a[4], const uint32_t b[2]) {
    asm volatile(
        "mma.sync.aligned.m16n8k16.row.col.f32.f16.f16.f32 "
        "{%0,%1,%2,%3}, {%4,%5,%6,%7}, {%8,%9}, {%0,%1,%2,%3};"
        : "+f"(c[0]), "+f"(c[1]), "+f"(c[2]), "+f"(c[3])
        : "r"(a[0]), "r"(a[1]), "r"(a[2]), "r"(a[3]), "r"(b[0]), "r"(b[1]));
}
__device__ __forceinline__ void ldsm_x4(uint32_t r[4], uint32_t saddr) {
    asm volatile("ldmatrix.sync.aligned.m8n8.x4.shared.b16 {%0,%1,%2,%3}, [%4];"
        : "=r"(r[0]), "=r"(r[1]), "=r"(r[2]), "=r"(r[3]) : "r"(saddr));
}
__device__ __forceinline__ void ldsm_x4t(uint32_t r[4], uint32_t saddr) {
    asm volatile("ldmatrix.sync.aligned.m8n8.x4.trans.shared.b16 {%0,%1,%2,%3}, [%4];"
        : "=r"(r[0]), "=r"(r[1]), "=r"(r[2]), "=r"(r[3]) : "r"(saddr));
}
__device__ __forceinline__ float ex2(float x) {
    float r; asm("ex2.approx.f32 %0, %1;" : "=f"(r) : "f"(x)); return r;
}
__device__ __forceinline__ uint32_t packh2(float a, float b) {
    __half2 h = __floats2half2_rn(a, b);
    return *(uint32_t*)&h;
}

// ---------------- prep: fp32 -> fp16 ----------------
__global__ void tohalf_kernel(const float2* __restrict__ in, __half2* __restrict__ out, int n2) {
    int i = blockIdx.x * blockDim.x + threadIdx.x;
    if (i >= n2) return;
    float2 v = in[i];
    out[i] = __floats2half2_rn(v.x, v.y);
}

// ---------------- rel-pos bias gather: (bias - 8) * log2e ----------------
__global__ void bias_kernel(const float* __restrict__ table,
                            const int*   __restrict__ ridx) {
    int nm = blockIdx.x * blockDim.x + threadIdx.x;
    if (nm >= NTOK * NTOK) return;
    int ri = ridx[nm];
    #pragma unroll
    for (int h = 0; h < NH; h++)
        g_bias[h * NTOK * NTOK + nm] = (table[ri * NH + h] - 8.0f) * LOG2E;
}

// ---------------- fp16 NT GEMM, BK=64, ldmatrix fragments ----------------
#define GRB 144                 // smem row bytes (64 halfs + pad)
#define GSTB (128 * GRB)        // stage size bytes
template<bool QKV_MODE>
__global__ __launch_bounds__(256, 2)
void gemm_f16(const __half* __restrict__ A, const __half* __restrict__ B,
              const float* __restrict__ bias, void* __restrict__ Cv,
              int M, int N, int K)
{
    extern __shared__ __half smh[];
    const uint32_t smem0 = (uint32_t)__cvta_generic_to_shared(smh);
    const uint32_t AsB = smem0;               // 2 stages A
    const uint32_t BsB = smem0 + 2 * GSTB;    // 2 stages B

    const int tid  = threadIdx.x;
    const int warp = tid >> 5, lane = tid & 31;
    const int qg   = lane >> 2, tg = lane & 3;
    const int wm   = (warp >> 2) * 64;
    const int wn   = (warp & 3) * 32;
    const int row0 = blockIdx.y * 128, col0 = blockIdx.x * 128;

    // ldmatrix per-lane offsets (bytes)
    const uint32_t aoff = (uint32_t)((lane & 15) * GRB + (lane >> 4) * 16) + (uint32_t)(wm * GRB);
    const uint32_t boff = (uint32_t)(((lane & 7) + 8 * ((lane >> 4) & 1)) * GRB
                                     + ((lane >> 3) & 1) * 16) + (uint32_t)(wn * GRB);

    float c[4][4][4];
    #pragma unroll
    for (int i = 0; i < 4; i++)
        #pragma unroll
        for (int j = 0; j < 4; j++)
            #pragma unroll
            for (int t = 0; t < 4; t++) c[i][j][t] = 0.0f;

    const int KT = K / 64;

    auto load_stage = [&](int stage, int k0) {
        #pragma unroll
        for (int i = 0; i < 4; i++) {
            int id = tid + i * 256;                // 1024 16B-chunks per matrix
            int r = id >> 3, c8 = (id & 7) * 8;    // halfs
            cp16(AsB + stage * GSTB + r * GRB + (id & 7) * 16,
                 A + (size_t)(row0 + r) * K + k0 + c8);
            cp16(BsB + stage * GSTB + r * GRB + (id & 7) * 16,
                 B + (size_t)(col0 + r) * K + k0 + c8);
        }
        cp_commit();
    };

    load_stage(0, 0);

    for (int kt = 0; kt < KT; kt++) {
        if (kt + 1 < KT) {
            load_stage((kt + 1) & 1, (kt + 1) * 64);
            asm volatile("cp.async.wait_group 1;");
        } else {
            asm volatile("cp.async.wait_group 0;");
        }
        __syncthreads();

        const uint32_t Asb = AsB + (kt & 1) * GSTB;
        const uint32_t Bsb = BsB + (kt & 1) * GSTB;

        #pragma unroll
        for (int ks = 0; ks < 4; ks++) {           // four k16 steps
            uint32_t af[4][4], bf[4][2];
            #pragma unroll
            for (int i = 0; i < 4; i++)
                ldsm_x4(af[i], Asb + aoff + i * 16 * GRB + ks * 32);
            #pragma unroll
            for (int jp = 0; jp < 2; jp++) {
                uint32_t bt[4];
                ldsm_x4(bt, Bsb + boff + jp * 16 * GRB + ks * 32);
                bf[2 * jp][0] = bt[0]; bf[2 * jp][1] = bt[1];
                bf[2 * jp + 1][0] = bt[2]; bf[2 * jp + 1][1] = bt[3];
            }
            #pragma unroll
            for (int i = 0; i < 4; i++)
                #pragma unroll
                for (int j = 0; j < 4; j++)
                    mma_f16(c[i][j], af[i], bf[j]);
        }
        __syncthreads();
    }

    const float qscale = (float)(0.17677669529663687 * 1.4426950408889634);
    #pragma unroll
    for (int i = 0; i < 4; i++) {
        int row = row0 + wm + i * 16 + qg;
        #pragma unroll
        for (int j = 0; j < 4; j++) {
            int col = col0 + wn + j * 8 + 2 * tg;
            float b0 = bias[col], b1 = bias[col + 1];
            float v00 = c[i][j][0] + b0, v01 = c[i][j][1] + b1;
            float v10 = c[i][j][2] + b0, v11 = c[i][j][3] + b1;
            if (QKV_MODE) {
                if (col < 256) { v00 *= qscale; v01 *= qscale; v10 *= qscale; v11 *= qscale; }
                __half* C = (__half*)Cv;
                *(__half2*)&C[(size_t)row * N + col]       = __floats2half2_rn(v00, v01);
                *(__half2*)&C[(size_t)(row + 8) * N + col] = __floats2half2_rn(v10, v11);
            } else {
                float* C = (float*)Cv;
                *(float2*)&C[(size_t)row * N + col]       = make_float2(v00, v01);
                *(float2*)&C[(size_t)(row + 8) * N + col] = make_float2(v10, v11);
            }
        }
    }
}

// ---------------- fp16 flash attention: ldmatrix + register-resident P --------
// CTA per (b,h), 8 warps x 32 rows. K/V/Q staged stride 40 halfs (80B, ldsm-CF).
#define ARB 80                   // row bytes for Q/K/V tiles
__global__ __launch_bounds__(256, 2)
void attn_f16(const float* __restrict__ mask)
{
    extern __shared__ __half smh[];
    const uint32_t smem0 = (uint32_t)__cvta_generic_to_shared(smh);
    const uint32_t QsB = smem0;                 // 256*80B
    const uint32_t KsB = smem0 + 256 * ARB;
    const uint32_t VsB = smem0 + 2 * 256 * ARB;

    const int bh = blockIdx.x, b = bh >> 3, h = bh & 7;
    const int tid = threadIdx.x, warp = tid >> 5, lane = tid & 31;
    const int qg = lane >> 2, tg = lane & 3;

    const __half* base = g_qkv + (size_t)b * NTOK * QKVD + h * 32;

    // stage Q, K, V coalesced (256 rows x 64B each)
    #pragma unroll
    for (int i = 0; i < 4; i++) {
        int id = tid + i * 256;
        int m = id >> 2, cb = (id & 3) * 16;       // byte col
        const __half* src = base + m * QKVD + (id & 3) * 8;
        cp16(QsB + m * ARB + cb, src);
        cp16(KsB + m * ARB + cb, src + 256);
        cp16(VsB + m * ARB + cb, src + 512);
    }
    cp_commit();
    asm volatile("cp.async.wait_group 0;");
    __syncthreads();

    const int wm = warp * 32;
    const float* bias_h = g_bias + (size_t)h * NTOK * NTOK;
    const float* mask_w = mask + (size_t)(b & 63) * NTOK * NTOK;

    // per-lane ldsm offsets (bytes)
    const uint32_t aoff = (uint32_t)((lane & 15) * ARB + (lane >> 4) * 16);           // A-pattern
    const uint32_t koff = (uint32_t)(((lane & 7) + 8 * ((lane >> 4) & 1)) * ARB
                                     + ((lane >> 3) & 1) * 16);                        // B-pattern
    const uint32_t voff = aoff;                                                        // trans pattern

    // persistent Q fragments via ldmatrix
    uint32_t qf[2][2][4];
    #pragma unroll
    for (int i = 0; i < 2; i++)
        #pragma unroll
        for (int ks = 0; ks < 2; ks++)
            ldsm_x4(qf[i][ks], QsB + aoff + (wm + 16 * i) * ARB + ks * 32);

    float O[2][4][4];
    #pragma unroll
    for (int i = 0; i < 2; i++)
        #pragma unroll
        for (int j = 0; j < 4; j++)
            #pragma unroll
            for (int t = 0; t < 4; t++) O[i][j][t] = 0.0f;
    float lrun[4] = {0.f, 0.f, 0.f, 0.f};

    #pragma unroll 1
    for (int nb = 0; nb < 8; nb++) {
        const int n0 = nb * 32;

        // ---- S init: bias' + mask*log2e  (bias' pre-shifted & scaled)
        float S[2][4][4];
        #pragma unroll
        for (int i = 0; i < 2; i++) {
            int row = wm + 16 * i + qg;
            #pragma unroll
            for (int j = 0; j < 4; j++) {
                int col = n0 + 8 * j + 2 * tg;
                float2 b0 = *(const float2*)(bias_h + (size_t)row * NTOK + col);
                float2 m0 = *(const float2*)(mask_w + (size_t)row * NTOK + col);
                float2 b1 = *(const float2*)(bias_h + (size_t)(row + 8) * NTOK + col);
                float2 m1 = *(const float2*)(mask_w + (size_t)(row + 8) * NTOK + col);
                S[i][j][0] = fmaf(m0.x, LOG2E, b0.x);
                S[i][j][1] = fmaf(m0.y, LOG2E, b0.y);
                S[i][j][2] = fmaf(m1.x, LOG2E, b1.x);
                S[i][j][3] = fmaf(m1.y, LOG2E, b1.y);
            }
        }

        // ---- K fragments (B operand): 4 x LDSM.x4
        uint32_t kf[2][4][2];      // [ks][j][2]
        #pragma unroll
        for (int ks = 0; ks < 2; ks++)
            #pragma unroll
            for (int jp = 0; jp < 2; jp++) {
                uint32_t t4[4];
                ldsm_x4(t4, KsB + koff + (n0 + 16 * jp) * ARB + ks * 32);
                kf[ks][2 * jp][0] = t4[0]; kf[ks][2 * jp][1] = t4[1];
                kf[ks][2 * jp + 1][0] = t4[2]; kf[ks][2 * jp + 1][1] = t4[3];
            }

        // ---- S += Q K^T
        #pragma unroll
        for (int ks = 0; ks < 2; ks++)
            #pragma unroll
            for (int j = 0; j < 4; j++) {
                mma_f16(S[0][j], qf[0][ks], kf[ks][j]);
                mma_f16(S[1][j], qf[1][ks], kf[ks][j]);
            }

        // ---- fixed-max softmax: p = 2^S, packed straight into A-fragments
        uint32_t ph[2][2][4];      // [i][ks2][4] = PV A-fragments
        #pragma unroll
        for (int i = 0; i < 2; i++) {
            float ps0 = 0.f, ps1 = 0.f;
            #pragma unroll
            for (int ks2 = 0; ks2 < 2; ks2++) {
                float e00 = ex2(S[i][2 * ks2][0]),     e01 = ex2(S[i][2 * ks2][1]);
                float e02 = ex2(S[i][2 * ks2][2]),     e03 = ex2(S[i][2 * ks2][3]);
                float e10 = ex2(S[i][2 * ks2 + 1][0]), e11 = ex2(S[i][2 * ks2 + 1][1]);
                float e12 = ex2(S[i][2 * ks2 + 1][2]), e13 = ex2(S[i][2 * ks2 + 1][3]);
                ps0 += (e00 + e01) + (e10 + e11);
                ps1 += (e02 + e03) + (e12 + e13);
                ph[i][ks2][0] = packh2(e00, e01);
                ph[i][ks2][1] = packh2(e02, e03);
                ph[i][ks2][2] = packh2(e10, e11);
                ph[i][ks2][3] = packh2(e12, e13);
            }
            ps0 += __shfl_xor_sync(0xffffffffu, ps0, 1);
            ps0 += __shfl_xor_sync(0xffffffffu, ps0, 2);
            ps1 += __shfl_xor_sync(0xffffffffu, ps1, 1);
            ps1 += __shfl_xor_sync(0xffffffffu, ps1, 2);
            lrun[2 * i]     += ps0;
            lrun[2 * i + 1] += ps1;
        }

        // ---- V fragments via ldmatrix.trans (B operand of PV)
        uint32_t vf[2][4][2];      // [ks2][j][2]
        #pragma unroll
        for (int ks2 = 0; ks2 < 2; ks2++)
            #pragma unroll
            for (int jp = 0; jp < 2; jp++) {
                uint32_t t4[4];
                ldsm_x4t(t4, VsB + voff + (n0 + 16 * ks2) * ARB + jp * 32);
                vf[ks2][2 * jp][0] = t4[0]; vf[ks2][2 * jp][1] = t4[1];
                vf[ks2][2 * jp + 1][0] = t4[2]; vf[ks2][2 * jp + 1][1] = t4[3];
            }

        // ---- O += P V
        #pragma unroll
        for (int ks2 = 0; ks2 < 2; ks2++)
            #pragma unroll
            for (int j = 0; j < 4; j++) {
                mma_f16(O[0][j], ph[0][ks2], vf[ks2][j]);
                mma_f16(O[1][j], ph[1][ks2], vf[ks2][j]);
            }
    }

    float inv[4];
    #pragma unroll
    for (int r = 0; r < 4; r++) inv[r] = 1.0f / lrun[r];

    #pragma unroll
    for (int i = 0; i < 2; i++) {
        int row = wm + 16 * i + qg;
        #pragma unroll
        for (int j = 0; j < 4; j++) {
            int col = h * 32 + 8 * j + 2 * tg;
            *(__half2*)&g_att[((size_t)b * NTOK + row) * CDIM + col] =
                __floats2half2_rn(O[i][j][0] * inv[2 * i], O[i][j][1] * inv[2 * i]);
            *(__half2*)&g_att[((size_t)b * NTOK + row + 8) * CDIM + col] =
                __floats2half2_rn(O[i][j][2] * inv[2 * i + 1], O[i][j][3] * inv[2 * i + 1]);
        }
    }
}

// --------------------------------------------------------------------------
extern "C" void kernel_launch(void* const* d_in, const int* in_sizes, int n_in,
                              void* d_out, int out_size)
{
    const float* x      = (const float*)d_in[0];
    const float* mask   = (const float*)d_in[1];
    const float* qkv_w  = (const float*)d_in[2];
    const float* qkv_b  = (const float*)d_in[3];
    const float* proj_w = (const float*)d_in[4];
    const float* proj_b = (const float*)d_in[5];
    const float* table  = (const float*)d_in[6];
    const int*   ridx   = (const int*)d_in[7];
    float* out = (float*)d_out;

    __half *qkv_ptr, *att_ptr, *xh_ptr, *wh_ptr;
    cudaGetSymbolAddress((void**)&qkv_ptr, g_qkv);
    cudaGetSymbolAddress((void**)&att_ptr, g_att);
    cudaGetSymbolAddress((void**)&xh_ptr,  g_xh);
    cudaGetSymbolAddress((void**)&wh_ptr,  g_wh);
    __half* qkvw_h  = wh_ptr;
    __half* projw_h = wh_ptr + QKVD * CDIM;

    const int gemm_smem = 4 * GSTB;           // 73728 B
    const int attn_smem = 3 * 256 * ARB;      // 61440 B
    cudaFuncSetAttribute((const void*)gemm_f16<true>,
                         cudaFuncAttributeMaxDynamicSharedMemorySize, gemm_smem);
    cudaFuncSetAttribute((const void*)gemm_f16<false>,
                         cudaFuncAttributeMaxDynamicSharedMemorySize, gemm_smem);
    cudaFuncSetAttribute((const void*)attn_f16,
                         cudaFuncAttributeMaxDynamicSharedMemorySize, attn_smem);

    // 0) prep: fp32 -> fp16
    tohalf_kernel<<<(NBATCH * NTOK * CDIM / 2 + 255) / 256, 256>>>(
        (const float2*)x, (__half2*)xh_ptr, NBATCH * NTOK * CDIM / 2);
    tohalf_kernel<<<(QKVD * CDIM / 2 + 255) / 256, 256>>>(
        (const float2*)qkv_w, (__half2*)qkvw_h, QKVD * CDIM / 2);
    tohalf_kernel<<<(CDIM * CDIM / 2 + 255) / 256, 256>>>(
        (const float2*)proj_w, (__half2*)projw_h, CDIM * CDIM / 2);

    // 1) rel-pos bias gather (pre-shifted, log2e-scaled)
    bias_kernel<<<(NTOK * NTOK + 255) / 256, 256>>>(table, ridx);

    // 2) QKV projection -> fp16 (Q pre-scaled by scale*log2e)
    gemm_f16<true><<<dim3(QKVD / 128, (NBATCH * NTOK) / 128), 256, gemm_smem>>>(
        xh_ptr, qkvw_h, qkv_b, qkv_ptr, NBATCH * NTOK, QKVD, CDIM);

    // 3) window attention
    attn_f16<<<NBATCH * NH, 256, attn_smem>>>(mask);

    // 4) output projection -> fp32 d_out
    gemm_f16<false><<<dim3(CDIM / 128, (NBATCH * NTOK) / 128), 256, gemm_smem>>>(
        att_ptr, projw_h, proj_b, out, NBATCH * NTOK, CDIM, CDIM);
}

// round 9
// speedup vs baseline: 1.7826x; 1.0185x over previous
#include <cuda_runtime.h>
#include <cuda_fp16.h>
#include <math.h>
#include <stdint.h>

#define NBATCH 192
#define NTOK   256
#define CDIM   256
#define NH     8
#define HD     32
#define QKVD   768   // 3*C

#define LOG2E 1.4426950408889634f

// ---------------- scratch (static __device__, no runtime alloc) ----------------
__device__ __half g_qkv [NBATCH * NTOK * QKVD];   // fp16, Q pre-scaled by scale*log2e
__device__ __half g_cmb [64 * NH * NTOK * NTOK];  // (bias-8+mask)*log2e, fp16
__device__ __half g_att [NBATCH * NTOK * CDIM];   // attention out fp16
__device__ __half g_xh  [NBATCH * NTOK * CDIM];   // x in fp16
__device__ __half g_wh  [QKVD * CDIM + CDIM * CDIM]; // fp16 qkv_w | proj_w

// ---------------- helpers ----------------
__device__ __forceinline__ void cp16(uint32_t saddr, const void* g) {
    asm volatile("cp.async.cg.shared.global [%0], [%1], 16;" :: "r"(saddr), "l"(g));
}
__device__ __forceinline__ void cp_commit() { asm volatile("cp.async.commit_group;"); }
__device__ __forceinline__ void mma_f16(float c[4], const uint32_t a[4], const uint32_t b[2]) {
    asm volatile(
        "mma.sync.aligned.m16n8k16.row.col.f32.f16.f16.f32 "
        "{%0,%1,%2,%3}, {%4,%5,%6,%7}, {%8,%9}, {%0,%1,%2,%3};"
        : "+f"(c[0]), "+f"(c[1]), "+f"(c[2]), "+f"(c[3])
        : "r"(a[0]), "r"(a[1]), "r"(a[2]), "r"(a[3]), "r"(b[0]), "r"(b[1]));
}
__device__ __forceinline__ void ldsm_x4(uint32_t r[4], uint32_t saddr) {
    asm volatile("ldmatrix.sync.aligned.m8n8.x4.shared.b16 {%0,%1,%2,%3}, [%4];"
        : "=r"(r[0]), "=r"(r[1]), "=r"(r[2]), "=r"(r[3]) : "r"(saddr));
}
__device__ __forceinline__ void ldsm_x4t(uint32_t r[4], uint32_t saddr) {
    asm volatile("ldmatrix.sync.aligned.m8n8.x4.trans.shared.b16 {%0,%1,%2,%3}, [%4];"
        : "=r"(r[0]), "=r"(r[1]), "=r"(r[2]), "=r"(r[3]) : "r"(saddr));
}
__device__ __forceinline__ float ex2(float x) {
    float r; asm("ex2.approx.f32 %0, %1;" : "=f"(r) : "f"(x)); return r;
}
__device__ __forceinline__ uint32_t packh2(float a, float b) {
    __half2 h = __floats2half2_rn(a, b);
    return *(uint32_t*)&h;
}

// ---------------- prep: fp32 -> fp16 ----------------
__global__ void tohalf_kernel(const float2* __restrict__ in, __half2* __restrict__ out, int n2) {
    int i = blockIdx.x * blockDim.x + threadIdx.x;
    if (i >= n2) return;
    float2 v = in[i];
    out[i] = __floats2half2_rn(v.x, v.y);
}

// ---------------- fused logit-bias table: (bias-8+mask)*log2e as half --------
// thread t handles token-pair nm = 2t; writes all 64 windows x 8 heads.
__global__ void cmb_kernel(const float* __restrict__ table,
                           const int*   __restrict__ ridx,
                           const float* __restrict__ mask) {
    int t = blockIdx.x * blockDim.x + threadIdx.x;
    if (t >= NTOK * NTOK / 2) return;
    int nm = t * 2;
    int r0 = ridx[nm], r1 = ridx[nm + 1];
    float b0[NH], b1[NH];
    #pragma unroll
    for (int h = 0; h < NH; h++) {
        b0[h] = (table[r0 * NH + h] - 8.0f) * LOG2E;
        b1[h] = (table[r1 * NH + h] - 8.0f) * LOG2E;
    }
    const float2* m2 = (const float2*)mask;
    __half2* c2 = (__half2*)g_cmb;
    #pragma unroll 1
    for (int w = 0; w < 64; w++) {
        float2 mm = m2[(w << 15) + t];
        float mx = mm.x * LOG2E, my = mm.y * LOG2E;
        #pragma unroll
        for (int h = 0; h < NH; h++)
            c2[(size_t)((w * NH + h) << 15) + t] =
                __floats2half2_rn(b0[h] + mx, b1[h] + my);
    }
}

// ---------------- fp16 NT GEMM, BK=64, ldmatrix fragments ----------------
#define GRB 144                 // smem row bytes (64 halfs + pad)
#define GSTB (128 * GRB)        // stage size bytes
template<bool QKV_MODE>
__global__ __launch_bounds__(256, 2)
void gemm_f16(const __half* __restrict__ A, const __half* __restrict__ B,
              const float* __restrict__ bias, void* __restrict__ Cv,
              int M, int N, int K)
{
    extern __shared__ __half smh[];
    const uint32_t smem0 = (uint32_t)__cvta_generic_to_shared(smh);
    const uint32_t AsB = smem0;               // 2 stages A
    const uint32_t BsB = smem0 + 2 * GSTB;    // 2 stages B

    const int tid  = threadIdx.x;
    const int warp = tid >> 5, lane = tid & 31;
    const int qg   = lane >> 2, tg = lane & 3;
    const int wm   = (warp >> 2) * 64;
    const int wn   = (warp & 3) * 32;
    const int row0 = blockIdx.y * 128, col0 = blockIdx.x * 128;

    const uint32_t aoff = (uint32_t)((lane & 15) * GRB + (lane >> 4) * 16) + (uint32_t)(wm * GRB);
    const uint32_t boff = (uint32_t)(((lane & 7) + 8 * ((lane >> 4) & 1)) * GRB
                                     + ((lane >> 3) & 1) * 16) + (uint32_t)(wn * GRB);

    float c[4][4][4];
    #pragma unroll
    for (int i = 0; i < 4; i++)
        #pragma unroll
        for (int j = 0; j < 4; j++)
            #pragma unroll
            for (int t = 0; t < 4; t++) c[i][j][t] = 0.0f;

    const int KT = K / 64;

    auto load_stage = [&](int stage, int k0) {
        #pragma unroll
        for (int i = 0; i < 4; i++) {
            int id = tid + i * 256;
            int r = id >> 3, c8 = (id & 7) * 8;
            cp16(AsB + stage * GSTB + r * GRB + (id & 7) * 16,
                 A + (size_t)(row0 + r) * K + k0 + c8);
            cp16(BsB + stage * GSTB + r * GRB + (id & 7) * 16,
                 B + (size_t)(col0 + r) * K + k0 + c8);
        }
        cp_commit();
    };

    load_stage(0, 0);

    for (int kt = 0; kt < KT; kt++) {
        if (kt + 1 < KT) {
            load_stage((kt + 1) & 1, (kt + 1) * 64);
            asm volatile("cp.async.wait_group 1;");
        } else {
            asm volatile("cp.async.wait_group 0;");
        }
        __syncthreads();

        const uint32_t Asb = AsB + (kt & 1) * GSTB;
        const uint32_t Bsb = BsB + (kt & 1) * GSTB;

        #pragma unroll
        for (int ks = 0; ks < 4; ks++) {
            uint32_t af[4][4], bf[4][2];
            #pragma unroll
            for (int i = 0; i < 4; i++)
                ldsm_x4(af[i], Asb + aoff + i * 16 * GRB + ks * 32);
            #pragma unroll
            for (int jp = 0; jp < 2; jp++) {
                uint32_t bt[4];
                ldsm_x4(bt, Bsb + boff + jp * 16 * GRB + ks * 32);
                bf[2 * jp][0] = bt[0]; bf[2 * jp][1] = bt[1];
                bf[2 * jp + 1][0] = bt[2]; bf[2 * jp + 1][1] = bt[3];
            }
            #pragma unroll
            for (int i = 0; i < 4; i++)
                #pragma unroll
                for (int j = 0; j < 4; j++)
                    mma_f16(c[i][j], af[i], bf[j]);
        }
        __syncthreads();
    }

    const float qscale = (float)(0.17677669529663687 * 1.4426950408889634);
    #pragma unroll
    for (int i = 0; i < 4; i++) {
        int row = row0 + wm + i * 16 + qg;
        #pragma unroll
        for (int j = 0; j < 4; j++) {
            int col = col0 + wn + j * 8 + 2 * tg;
            float b0 = bias[col], b1 = bias[col + 1];
            float v00 = c[i][j][0] + b0, v01 = c[i][j][1] + b1;
            float v10 = c[i][j][2] + b0, v11 = c[i][j][3] + b1;
            if (QKV_MODE) {
                if (col < 256) { v00 *= qscale; v01 *= qscale; v10 *= qscale; v11 *= qscale; }
                __half* C = (__half*)Cv;
                *(__half2*)&C[(size_t)row * N + col]       = __floats2half2_rn(v00, v01);
                *(__half2*)&C[(size_t)(row + 8) * N + col] = __floats2half2_rn(v10, v11);
            } else {
                float* C = (float*)Cv;
                *(float2*)&C[(size_t)row * N + col]       = make_float2(v00, v01);
                *(float2*)&C[(size_t)(row + 8) * N + col] = make_float2(v10, v11);
            }
        }
    }
}

// ---------------- fp16 flash attention: ldmatrix + register-resident P --------
#define ARB 80                   // row bytes for Q/K/V tiles
__global__ __launch_bounds__(256, 2)
void attn_f16()
{
    extern __shared__ __half smh[];
    const uint32_t smem0 = (uint32_t)__cvta_generic_to_shared(smh);
    const uint32_t QsB = smem0;                 // 256*80B
    const uint32_t KsB = smem0 + 256 * ARB;
    const uint32_t VsB = smem0 + 2 * 256 * ARB;

    const int bh = blockIdx.x, b = bh >> 3, h = bh & 7;
    const int tid = threadIdx.x, warp = tid >> 5, lane = tid & 31;
    const int qg = lane >> 2, tg = lane & 3;

    const __half* base = g_qkv + (size_t)b * NTOK * QKVD + h * 32;

    #pragma unroll
    for (int i = 0; i < 4; i++) {
        int id = tid + i * 256;
        int m = id >> 2, cb = (id & 3) * 16;
        const __half* src = base + m * QKVD + (id & 3) * 8;
        cp16(QsB + m * ARB + cb, src);
        cp16(KsB + m * ARB + cb, src + 256);
        cp16(VsB + m * ARB + cb, src + 512);
    }
    cp_commit();
    asm volatile("cp.async.wait_group 0;");
    __syncthreads();

    const int wm = warp * 32;
    // fused logit bias: half2 rows of 128 elements
    const __half2* cmb = (const __half2*)g_cmb + ((size_t)(((b & 63) * NH + h)) << 15);

    const uint32_t aoff = (uint32_t)((lane & 15) * ARB + (lane >> 4) * 16);
    const uint32_t koff = (uint32_t)(((lane & 7) + 8 * ((lane >> 4) & 1)) * ARB
                                     + ((lane >> 3) & 1) * 16);
    const uint32_t voff = aoff;

    uint32_t qf[2][2][4];
    #pragma unroll
    for (int i = 0; i < 2; i++)
        #pragma unroll
        for (int ks = 0; ks < 2; ks++)
            ldsm_x4(qf[i][ks], QsB + aoff + (wm + 16 * i) * ARB + ks * 32);

    float O[2][4][4];
    #pragma unroll
    for (int i = 0; i < 2; i++)
        #pragma unroll
        for (int j = 0; j < 4; j++)
            #pragma unroll
            for (int t = 0; t < 4; t++) O[i][j][t] = 0.0f;
    float lrun[4] = {0.f, 0.f, 0.f, 0.f};

    #pragma unroll 1
    for (int nb = 0; nb < 8; nb++) {
        const int n0 = nb * 32;

        // ---- S init from fused half table (one half2 per 2 cols)
        float S[2][4][4];
        #pragma unroll
        for (int i = 0; i < 2; i++) {
            int row = wm + 16 * i + qg;
            #pragma unroll
            for (int j = 0; j < 4; j++) {
                int ci = (n0 >> 1) + 4 * j + tg;
                float2 v0 = __half22float2(cmb[row * 128 + ci]);
                float2 v1 = __half22float2(cmb[(row + 8) * 128 + ci]);
                S[i][j][0] = v0.x;
                S[i][j][1] = v0.y;
                S[i][j][2] = v1.x;
                S[i][j][3] = v1.y;
            }
        }

        // ---- K fragments (B operand)
        uint32_t kf[2][4][2];
        #pragma unroll
        for (int ks = 0; ks < 2; ks++)
            #pragma unroll
            for (int jp = 0; jp < 2; jp++) {
                uint32_t t4[4];
                ldsm_x4(t4, KsB + koff + (n0 + 16 * jp) * ARB + ks * 32);
                kf[ks][2 * jp][0] = t4[0]; kf[ks][2 * jp][1] = t4[1];
                kf[ks][2 * jp + 1][0] = t4[2]; kf[ks][2 * jp + 1][1] = t4[3];
            }

        // ---- S += Q K^T
        #pragma unroll
        for (int ks = 0; ks < 2; ks++)
            #pragma unroll
            for (int j = 0; j < 4; j++) {
                mma_f16(S[0][j], qf[0][ks], kf[ks][j]);
                mma_f16(S[1][j], qf[1][ks], kf[ks][j]);
            }

        // ---- fixed-max softmax: p = 2^S packed into A-fragments
        uint32_t ph[2][2][4];
        #pragma unroll
        for (int i = 0; i < 2; i++) {
            float ps0 = 0.f, ps1 = 0.f;
            #pragma unroll
            for (int ks2 = 0; ks2 < 2; ks2++) {
                float e00 = ex2(S[i][2 * ks2][0]),     e01 = ex2(S[i][2 * ks2][1]);
                float e02 = ex2(S[i][2 * ks2][2]),     e03 = ex2(S[i][2 * ks2][3]);
                float e10 = ex2(S[i][2 * ks2 + 1][0]), e11 = ex2(S[i][2 * ks2 + 1][1]);
                float e12 = ex2(S[i][2 * ks2 + 1][2]), e13 = ex2(S[i][2 * ks2 + 1][3]);
                ps0 += (e00 + e01) + (e10 + e11);
                ps1 += (e02 + e03) + (e12 + e13);
                ph[i][ks2][0] = packh2(e00, e01);
                ph[i][ks2][1] = packh2(e02, e03);
                ph[i][ks2][2] = packh2(e10, e11);
                ph[i][ks2][3] = packh2(e12, e13);
            }
            ps0 += __shfl_xor_sync(0xffffffffu, ps0, 1);
            ps0 += __shfl_xor_sync(0xffffffffu, ps0, 2);
            ps1 += __shfl_xor_sync(0xffffffffu, ps1, 1);
            ps1 += __shfl_xor_sync(0xffffffffu, ps1, 2);
            lrun[2 * i]     += ps0;
            lrun[2 * i + 1] += ps1;
        }

        // ---- V fragments via ldmatrix.trans
        uint32_t vf[2][4][2];
        #pragma unroll
        for (int ks2 = 0; ks2 < 2; ks2++)
            #pragma unroll
            for (int jp = 0; jp < 2; jp++) {
                uint32_t t4[4];
                ldsm_x4t(t4, VsB + voff + (n0 + 16 * ks2) * ARB + jp * 32);
                vf[ks2][2 * jp][0] = t4[0]; vf[ks2][2 * jp][1] = t4[1];
                vf[ks2][2 * jp + 1][0] = t4[2]; vf[ks2][2 * jp + 1][1] = t4[3];
            }

        // ---- O += P V
        #pragma unroll
        for (int ks2 = 0; ks2 < 2; ks2++)
            #pragma unroll
            for (int j = 0; j < 4; j++) {
                mma_f16(O[0][j], ph[0][ks2], vf[ks2][j]);
                mma_f16(O[1][j], ph[1][ks2], vf[ks2][j]);
            }
    }

    float inv[4];
    #pragma unroll
    for (int r = 0; r < 4; r++) inv[r] = 1.0f / lrun[r];

    #pragma unroll
    for (int i = 0; i < 2; i++) {
        int row = wm + 16 * i + qg;
        #pragma unroll
        for (int j = 0; j < 4; j++) {
            int col = h * 32 + 8 * j + 2 * tg;
            *(__half2*)&g_att[((size_t)b * NTOK + row) * CDIM + col] =
                __floats2half2_rn(O[i][j][0] * inv[2 * i], O[i][j][1] * inv[2 * i]);
            *(__half2*)&g_att[((size_t)b * NTOK + row + 8) * CDIM + col] =
                __floats2half2_rn(O[i][j][2] * inv[2 * i + 1], O[i][j][3] * inv[2 * i + 1]);
        }
    }
}

// --------------------------------------------------------------------------
extern "C" void kernel_launch(void* const* d_in, const int* in_sizes, int n_in,
                              void* d_out, int out_size)
{
    const float* x      = (const float*)d_in[0];
    const float* mask   = (const float*)d_in[1];
    const float* qkv_w  = (const float*)d_in[2];
    const float* qkv_b  = (const float*)d_in[3];
    const float* proj_w = (const float*)d_in[4];
    const float* proj_b = (const float*)d_in[5];
    const float* table  = (const float*)d_in[6];
    const int*   ridx   = (const int*)d_in[7];
    float* out = (float*)d_out;

    __half *qkv_ptr, *att_ptr, *xh_ptr, *wh_ptr;
    cudaGetSymbolAddress((void**)&qkv_ptr, g_qkv);
    cudaGetSymbolAddress((void**)&att_ptr, g_att);
    cudaGetSymbolAddress((void**)&xh_ptr,  g_xh);
    cudaGetSymbolAddress((void**)&wh_ptr,  g_wh);
    __half* qkvw_h  = wh_ptr;
    __half* projw_h = wh_ptr + QKVD * CDIM;

    const int gemm_smem = 4 * GSTB;           // 73728 B
    const int attn_smem = 3 * 256 * ARB;      // 61440 B
    cudaFuncSetAttribute((const void*)gemm_f16<true>,
                         cudaFuncAttributeMaxDynamicSharedMemorySize, gemm_smem);
    cudaFuncSetAttribute((const void*)gemm_f16<false>,
                         cudaFuncAttributeMaxDynamicSharedMemorySize, gemm_smem);
    cudaFuncSetAttribute((const void*)attn_f16,
                         cudaFuncAttributeMaxDynamicSharedMemorySize, attn_smem);

    // 0) prep: fp32 -> fp16 + fused logit-bias table
    tohalf_kernel<<<(NBATCH * NTOK * CDIM / 2 + 255) / 256, 256>>>(
        (const float2*)x, (__half2*)xh_ptr, NBATCH * NTOK * CDIM / 2);
    tohalf_kernel<<<(QKVD * CDIM / 2 + 255) / 256, 256>>>(
        (const float2*)qkv_w, (__half2*)qkvw_h, QKVD * CDIM / 2);
    tohalf_kernel<<<(CDIM * CDIM / 2 + 255) / 256, 256>>>(
        (const float2*)proj_w, (__half2*)projw_h, CDIM * CDIM / 2);
    cmb_kernel<<<(NTOK * NTOK / 2 + 255) / 256, 256>>>(table, ridx, mask);

    // 2) QKV projection -> fp16 (Q pre-scaled by scale*log2e)
    gemm_f16<true><<<dim3(QKVD / 128, (NBATCH * NTOK) / 128), 256, gemm_smem>>>(
        xh_ptr, qkvw_h, qkv_b, qkv_ptr, NBATCH * NTOK, QKVD, CDIM);

    // 3) window attention
    attn_f16<<<NBATCH * NH, 256, attn_smem>>>();

    // 4) output projection -> fp32 d_out
    gemm_f16<false><<<dim3(CDIM / 128, (NBATCH * NTOK) / 128), 256, gemm_smem>>>(
        att_ptr, projw_h, proj_b, out, NBATCH * NTOK, CDIM, CDIM);
}

// round 10
// speedup vs baseline: 1.7937x; 1.0063x over previous
#include <cuda_runtime.h>
#include <cuda_fp16.h>
#include <math.h>
#include <stdint.h>

#define NBATCH 192
#define NTOK   256
#define CDIM   256
#define NH     8
#define HD     32
#define QKVD   768   // 3*C

#define LOG2E 1.4426950408889634f
#define SHIFT (-8.0f * 1.4426950408889634f)   // overflow-guard, applied in-kernel

// ---------------- scratch (static __device__, no runtime alloc) ----------------
__device__ __half g_qkv [NBATCH * NTOK * QKVD];   // fp16, Q pre-scaled by scale*log2e
__device__ __half g_cmb [64 * NH * NTOK * NTOK];  // (bias+mask)*log2e, fp16 (unshifted)
__device__ __half g_att [NBATCH * NTOK * CDIM];   // attention out fp16
__device__ __half g_xh  [NBATCH * NTOK * CDIM];   // x in fp16
__device__ __half g_wh  [QKVD * CDIM + CDIM * CDIM]; // fp16 qkv_w | proj_w

// ---------------- helpers ----------------
__device__ __forceinline__ void cp16(uint32_t saddr, const void* g) {
    asm volatile("cp.async.cg.shared.global [%0], [%1], 16;" :: "r"(saddr), "l"(g));
}
__device__ __forceinline__ void cp_commit() { asm volatile("cp.async.commit_group;"); }
__device__ __forceinline__ void mma_f16(float c[4], const uint32_t a[4], const uint32_t b[2]) {
    asm volatile(
        "mma.sync.aligned.m16n8k16.row.col.f32.f16.f16.f32 "
        "{%0,%1,%2,%3}, {%4,%5,%6,%7}, {%8,%9}, {%0,%1,%2,%3};"
        : "+f"(c[0]), "+f"(c[1]), "+f"(c[2]), "+f"(c[3])
        : "r"(a[0]), "r"(a[1]), "r"(a[2]), "r"(a[3]), "r"(b[0]), "r"(b[1]));
}
__device__ __forceinline__ void ldsm_x4(uint32_t r[4], uint32_t saddr) {
    asm volatile("ldmatrix.sync.aligned.m8n8.x4.shared.b16 {%0,%1,%2,%3}, [%4];"
        : "=r"(r[0]), "=r"(r[1]), "=r"(r[2]), "=r"(r[3]) : "r"(saddr));
}
__device__ __forceinline__ void ldsm_x4t(uint32_t r[4], uint32_t saddr) {
    asm volatile("ldmatrix.sync.aligned.m8n8.x4.trans.shared.b16 {%0,%1,%2,%3}, [%4];"
        : "=r"(r[0]), "=r"(r[1]), "=r"(r[2]), "=r"(r[3]) : "r"(saddr));
}
__device__ __forceinline__ float ex2(float x) {
    float r; asm("ex2.approx.f32 %0, %1;" : "=f"(r) : "f"(x)); return r;
}
__device__ __forceinline__ uint32_t packh2(float a, float b) {
    __half2 h = __floats2half2_rn(a, b);
    return *(uint32_t*)&h;
}

// ---------------- prep: fp32 -> fp16 ----------------
__global__ void tohalf_kernel(const float2* __restrict__ in, __half2* __restrict__ out, int n2) {
    int i = blockIdx.x * blockDim.x + threadIdx.x;
    if (i >= n2) return;
    float2 v = in[i];
    out[i] = __floats2half2_rn(v.x, v.y);
}

// ---------------- fused logit-bias table v2: (bias+mask)*log2e as half -------
// grid (128, 64): blockIdx.y = window; thread t = half2 index within (N,N)/2.
__global__ void cmb_kernel(const float* __restrict__ table,
                           const int*   __restrict__ ridx,
                           const float* __restrict__ mask) {
    int t = blockIdx.x * blockDim.x + threadIdx.x;   // 0..32767
    int w = blockIdx.y;
    int nm = t * 2;
    int r0 = ridx[nm], r1 = ridx[nm + 1];
    float2 mm = ((const float2*)mask)[((size_t)w << 15) + t];
    float mx = mm.x * LOG2E, my = mm.y * LOG2E;
    __half2* c2 = (__half2*)g_cmb + ((size_t)(w * NH) << 15);
    #pragma unroll
    for (int h = 0; h < NH; h++) {
        float b0 = fmaf(table[r0 * NH + h], LOG2E, mx);
        float b1 = fmaf(table[r1 * NH + h], LOG2E, my);
        c2[((size_t)h << 15) + t] = __floats2half2_rn(b0, b1);
    }
}

// ---------------- fp16 NT GEMM, BK=64, ldmatrix fragments ----------------
#define GRB 144                 // smem row bytes (64 halfs + pad)
#define GSTB (128 * GRB)        // stage size bytes
template<bool QKV_MODE>
__global__ __launch_bounds__(256, 2)
void gemm_f16(const __half* __restrict__ A, const __half* __restrict__ B,
              const float* __restrict__ bias, void* __restrict__ Cv,
              int M, int N, int K)
{
    extern __shared__ __half smh[];
    const uint32_t smem0 = (uint32_t)__cvta_generic_to_shared(smh);
    const uint32_t AsB = smem0;               // 2 stages A
    const uint32_t BsB = smem0 + 2 * GSTB;    // 2 stages B

    const int tid  = threadIdx.x;
    const int warp = tid >> 5, lane = tid & 31;
    const int qg   = lane >> 2, tg = lane & 3;
    const int wm   = (warp >> 2) * 64;
    const int wn   = (warp & 3) * 32;
    const int row0 = blockIdx.y * 128, col0 = blockIdx.x * 128;

    const uint32_t aoff = (uint32_t)((lane & 15) * GRB + (lane >> 4) * 16) + (uint32_t)(wm * GRB);
    const uint32_t boff = (uint32_t)(((lane & 7) + 8 * ((lane >> 4) & 1)) * GRB
                                     + ((lane >> 3) & 1) * 16) + (uint32_t)(wn * GRB);

    float c[4][4][4];
    #pragma unroll
    for (int i = 0; i < 4; i++)
        #pragma unroll
        for (int j = 0; j < 4; j++)
            #pragma unroll
            for (int t = 0; t < 4; t++) c[i][j][t] = 0.0f;

    const int KT = K / 64;

    auto load_stage = [&](int stage, int k0) {
        #pragma unroll
        for (int i = 0; i < 4; i++) {
            int id = tid + i * 256;
            int r = id >> 3, c8 = (id & 7) * 8;
            cp16(AsB + stage * GSTB + r * GRB + (id & 7) * 16,
                 A + (size_t)(row0 + r) * K + k0 + c8);
            cp16(BsB + stage * GSTB + r * GRB + (id & 7) * 16,
                 B + (size_t)(col0 + r) * K + k0 + c8);
        }
        cp_commit();
    };

    load_stage(0, 0);

    for (int kt = 0; kt < KT; kt++) {
        if (kt + 1 < KT) {
            load_stage((kt + 1) & 1, (kt + 1) * 64);
            asm volatile("cp.async.wait_group 1;");
        } else {
            asm volatile("cp.async.wait_group 0;");
        }
        __syncthreads();

        const uint32_t Asb = AsB + (kt & 1) * GSTB;
        const uint32_t Bsb = BsB + (kt & 1) * GSTB;

        #pragma unroll
        for (int ks = 0; ks < 4; ks++) {
            uint32_t af[4][4], bf[4][2];
            #pragma unroll
            for (int i = 0; i < 4; i++)
                ldsm_x4(af[i], Asb + aoff + i * 16 * GRB + ks * 32);
            #pragma unroll
            for (int jp = 0; jp < 2; jp++) {
                uint32_t bt[4];
                ldsm_x4(bt, Bsb + boff + jp * 16 * GRB + ks * 32);
                bf[2 * jp][0] = bt[0]; bf[2 * jp][1] = bt[1];
                bf[2 * jp + 1][0] = bt[2]; bf[2 * jp + 1][1] = bt[3];
            }
            #pragma unroll
            for (int i = 0; i < 4; i++)
                #pragma unroll
                for (int j = 0; j < 4; j++)
                    mma_f16(c[i][j], af[i], bf[j]);
        }
        __syncthreads();
    }

    const float qscale = (float)(0.17677669529663687 * 1.4426950408889634);
    #pragma unroll
    for (int i = 0; i < 4; i++) {
        int row = row0 + wm + i * 16 + qg;
        #pragma unroll
        for (int j = 0; j < 4; j++) {
            int col = col0 + wn + j * 8 + 2 * tg;
            float b0 = bias[col], b1 = bias[col + 1];
            float v00 = c[i][j][0] + b0, v01 = c[i][j][1] + b1;
            float v10 = c[i][j][2] + b0, v11 = c[i][j][3] + b1;
            if (QKV_MODE) {
                if (col < 256) { v00 *= qscale; v01 *= qscale; v10 *= qscale; v11 *= qscale; }
                __half* C = (__half*)Cv;
                *(__half2*)&C[(size_t)row * N + col]       = __floats2half2_rn(v00, v01);
                *(__half2*)&C[(size_t)(row + 8) * N + col] = __floats2half2_rn(v10, v11);
            } else {
                float* C = (float*)Cv;
                *(float2*)&C[(size_t)row * N + col]       = make_float2(v00, v01);
                *(float2*)&C[(size_t)(row + 8) * N + col] = make_float2(v10, v11);
            }
        }
    }
}

// ---------------- fp16 flash attention: ldmatrix + register-resident P --------
#define ARB 80                   // row bytes for Q/K/V tiles
__global__ __launch_bounds__(256, 2)
void attn_f16()
{
    extern __shared__ __half smh[];
    const uint32_t smem0 = (uint32_t)__cvta_generic_to_shared(smh);
    const uint32_t QsB = smem0;                 // 256*80B
    const uint32_t KsB = smem0 + 256 * ARB;
    const uint32_t VsB = smem0 + 2 * 256 * ARB;

    const int bh = blockIdx.x, b = bh >> 3, h = bh & 7;
    const int tid = threadIdx.x, warp = tid >> 5, lane = tid & 31;
    const int qg = lane >> 2, tg = lane & 3;

    const __half* base = g_qkv + (size_t)b * NTOK * QKVD + h * 32;

    #pragma unroll
    for (int i = 0; i < 4; i++) {
        int id = tid + i * 256;
        int m = id >> 2, cb = (id & 3) * 16;
        const __half* src = base + m * QKVD + (id & 3) * 8;
        cp16(QsB + m * ARB + cb, src);
        cp16(KsB + m * ARB + cb, src + 256);
        cp16(VsB + m * ARB + cb, src + 512);
    }
    cp_commit();
    asm volatile("cp.async.wait_group 0;");
    __syncthreads();

    const int wm = warp * 32;
    const __half2* cmb = (const __half2*)g_cmb + ((size_t)(((b & 63) * NH + h)) << 15);

    const uint32_t aoff = (uint32_t)((lane & 15) * ARB + (lane >> 4) * 16);
    const uint32_t koff = (uint32_t)(((lane & 7) + 8 * ((lane >> 4) & 1)) * ARB
                                     + ((lane >> 3) & 1) * 16);
    const uint32_t voff = aoff;

    uint32_t qf[2][2][4];
    #pragma unroll
    for (int i = 0; i < 2; i++)
        #pragma unroll
        for (int ks = 0; ks < 2; ks++)
            ldsm_x4(qf[i][ks], QsB + aoff + (wm + 16 * i) * ARB + ks * 32);

    float O[2][4][4];
    #pragma unroll
    for (int i = 0; i < 2; i++)
        #pragma unroll
        for (int j = 0; j < 4; j++)
            #pragma unroll
            for (int t = 0; t < 4; t++) O[i][j][t] = 0.0f;
    float lrun[4] = {0.f, 0.f, 0.f, 0.f};

    #pragma unroll 1
    for (int nb = 0; nb < 8; nb++) {
        const int n0 = nb * 32;

        // ---- S init from fused half table + overflow-guard shift
        float S[2][4][4];
        #pragma unroll
        for (int i = 0; i < 2; i++) {
            int row = wm + 16 * i + qg;
            #pragma unroll
            for (int j = 0; j < 4; j++) {
                int ci = (n0 >> 1) + 4 * j + tg;
                float2 v0 = __half22float2(cmb[row * 128 + ci]);
                float2 v1 = __half22float2(cmb[(row + 8) * 128 + ci]);
                S[i][j][0] = v0.x + SHIFT;
                S[i][j][1] = v0.y + SHIFT;
                S[i][j][2] = v1.x + SHIFT;
                S[i][j][3] = v1.y + SHIFT;
            }
        }

        // ---- K fragments (B operand)
        uint32_t kf[2][4][2];
        #pragma unroll
        for (int ks = 0; ks < 2; ks++)
            #pragma unroll
            for (int jp = 0; jp < 2; jp++) {
                uint32_t t4[4];
                ldsm_x4(t4, KsB + koff + (n0 + 16 * jp) * ARB + ks * 32);
                kf[ks][2 * jp][0] = t4[0]; kf[ks][2 * jp][1] = t4[1];
                kf[ks][2 * jp + 1][0] = t4[2]; kf[ks][2 * jp + 1][1] = t4[3];
            }

        // ---- S += Q K^T
        #pragma unroll
        for (int ks = 0; ks < 2; ks++)
            #pragma unroll
            for (int j = 0; j < 4; j++) {
                mma_f16(S[0][j], qf[0][ks], kf[ks][j]);
                mma_f16(S[1][j], qf[1][ks], kf[ks][j]);
            }

        // ---- fixed-max softmax: p = 2^S packed into A-fragments
        uint32_t ph[2][2][4];
        #pragma unroll
        for (int i = 0; i < 2; i++) {
            float ps0 = 0.f, ps1 = 0.f;
            #pragma unroll
            for (int ks2 = 0; ks2 < 2; ks2++) {
                float e00 = ex2(S[i][2 * ks2][0]),     e01 = ex2(S[i][2 * ks2][1]);
                float e02 = ex2(S[i][2 * ks2][2]),     e03 = ex2(S[i][2 * ks2][3]);
                float e10 = ex2(S[i][2 * ks2 + 1][0]), e11 = ex2(S[i][2 * ks2 + 1][1]);
                float e12 = ex2(S[i][2 * ks2 + 1][2]), e13 = ex2(S[i][2 * ks2 + 1][3]);
                ps0 += (e00 + e01) + (e10 + e11);
                ps1 += (e02 + e03) + (e12 + e13);
                ph[i][ks2][0] = packh2(e00, e01);
                ph[i][ks2][1] = packh2(e02, e03);
                ph[i][ks2][2] = packh2(e10, e11);
                ph[i][ks2][3] = packh2(e12, e13);
            }
            ps0 += __shfl_xor_sync(0xffffffffu, ps0, 1);
            ps0 += __shfl_xor_sync(0xffffffffu, ps0, 2);
            ps1 += __shfl_xor_sync(0xffffffffu, ps1, 1);
            ps1 += __shfl_xor_sync(0xffffffffu, ps1, 2);
            lrun[2 * i]     += ps0;
            lrun[2 * i + 1] += ps1;
        }

        // ---- V fragments via ldmatrix.trans
        uint32_t vf[2][4][2];
        #pragma unroll
        for (int ks2 = 0; ks2 < 2; ks2++)
            #pragma unroll
            for (int jp = 0; jp < 2; jp++) {
                uint32_t t4[4];
                ldsm_x4t(t4, VsB + voff + (n0 + 16 * ks2) * ARB + jp * 32);
                vf[ks2][2 * jp][0] = t4[0]; vf[ks2][2 * jp][1] = t4[1];
                vf[ks2][2 * jp + 1][0] = t4[2]; vf[ks2][2 * jp + 1][1] = t4[3];
            }

        // ---- O += P V
        #pragma unroll
        for (int ks2 = 0; ks2 < 2; ks2++)
            #pragma unroll
            for (int j = 0; j < 4; j++) {
                mma_f16(O[0][j], ph[0][ks2], vf[ks2][j]);
                mma_f16(O[1][j], ph[1][ks2], vf[ks2][j]);
            }
    }

    float inv[4];
    #pragma unroll
    for (int r = 0; r < 4; r++) inv[r] = 1.0f / lrun[r];

    #pragma unroll
    for (int i = 0; i < 2; i++) {
        int row = wm + 16 * i + qg;
        #pragma unroll
        for (int j = 0; j < 4; j++) {
            int col = h * 32 + 8 * j + 2 * tg;
            *(__half2*)&g_att[((size_t)b * NTOK + row) * CDIM + col] =
                __floats2half2_rn(O[i][j][0] * inv[2 * i], O[i][j][1] * inv[2 * i]);
            *(__half2*)&g_att[((size_t)b * NTOK + row + 8) * CDIM + col] =
                __floats2half2_rn(O[i][j][2] * inv[2 * i + 1], O[i][j][3] * inv[2 * i + 1]);
        }
    }
}

// --------------------------------------------------------------------------
extern "C" void kernel_launch(void* const* d_in, const int* in_sizes, int n_in,
                              void* d_out, int out_size)
{
    const float* x      = (const float*)d_in[0];
    const float* mask   = (const float*)d_in[1];
    const float* qkv_w  = (const float*)d_in[2];
    const float* qkv_b  = (const float*)d_in[3];
    const float* proj_w = (const float*)d_in[4];
    const float* proj_b = (const float*)d_in[5];
    const float* table  = (const float*)d_in[6];
    const int*   ridx   = (const int*)d_in[7];
    float* out = (float*)d_out;

    __half *qkv_ptr, *att_ptr, *xh_ptr, *wh_ptr;
    cudaGetSymbolAddress((void**)&qkv_ptr, g_qkv);
    cudaGetSymbolAddress((void**)&att_ptr, g_att);
    cudaGetSymbolAddress((void**)&xh_ptr,  g_xh);
    cudaGetSymbolAddress((void**)&wh_ptr,  g_wh);
    __half* qkvw_h  = wh_ptr;
    __half* projw_h = wh_ptr + QKVD * CDIM;

    const int gemm_smem = 4 * GSTB;           // 73728 B
    const int attn_smem = 3 * 256 * ARB;      // 61440 B
    cudaFuncSetAttribute((const void*)gemm_f16<true>,
                         cudaFuncAttributeMaxDynamicSharedMemorySize, gemm_smem);
    cudaFuncSetAttribute((const void*)gemm_f16<false>,
                         cudaFuncAttributeMaxDynamicSharedMemorySize, gemm_smem);
    cudaFuncSetAttribute((const void*)attn_f16,
                         cudaFuncAttributeMaxDynamicSharedMemorySize, attn_smem);

    // 0) prep: fp32 -> fp16 + fused logit-bias table (parallel over windows)
    tohalf_kernel<<<(NBATCH * NTOK * CDIM / 2 + 255) / 256, 256>>>(
        (const float2*)x, (__half2*)xh_ptr, NBATCH * NTOK * CDIM / 2);
    tohalf_kernel<<<(QKVD * CDIM / 2 + 255) / 256, 256>>>(
        (const float2*)qkv_w, (__half2*)qkvw_h, QKVD * CDIM / 2);
    tohalf_kernel<<<(CDIM * CDIM / 2 + 255) / 256, 256>>>(
        (const float2*)proj_w, (__half2*)projw_h, CDIM * CDIM / 2);
    cmb_kernel<<<dim3(128, 64), 256>>>(table, ridx, mask);

    // 2) QKV projection -> fp16 (Q pre-scaled by scale*log2e)
    gemm_f16<true><<<dim3(QKVD / 128, (NBATCH * NTOK) / 128), 256, gemm_smem>>>(
        xh_ptr, qkvw_h, qkv_b, qkv_ptr, NBATCH * NTOK, QKVD, CDIM);

    // 3) window attention
    attn_f16<<<NBATCH * NH, 256, attn_smem>>>();

    // 4) output projection -> fp32 d_out
    gemm_f16<false><<<dim3(CDIM / 128, (NBATCH * NTOK) / 128), 256, gemm_smem>>>(
        att_ptr, projw_h, proj_b, out, NBATCH * NTOK, CDIM, CDIM);
}

// round 11
// speedup vs baseline: 1.9703x; 1.0985x over previous
#include <cuda_runtime.h>
#include <cuda_fp16.h>
#include <math.h>
#include <stdint.h>

#define NBATCH 192
#define NTOK   256
#define CDIM   256
#define NH     8
#define HD     32
#define QKVD   768   // 3*C

#define LOG2E 1.4426950408889634f
#define SHIFT (-4.0f * 1.4426950408889634f)   // overflow-guard (half-domain safe)

// ---------------- scratch (static __device__, no runtime alloc) ----------------
__device__ __half g_qkv  [NBATCH * NTOK * QKVD];   // fp16, Q pre-scaled by scale*log2e
__device__ __half g_cmb  [64 * NH * NTOK * NTOK];  // (bias+mask)*log2e, fp16
__device__ __half g_biasb[NTOK * NTOK * NH];       // bias*log2e, [token-pair][head] fp16
__device__ __half g_att  [NBATCH * NTOK * CDIM];   // attention out fp16
__device__ __half g_xh   [NBATCH * NTOK * CDIM];   // x in fp16
__device__ __half g_wh   [QKVD * CDIM + CDIM * CDIM]; // fp16 qkv_w | proj_w

// ---------------- helpers ----------------
__device__ __forceinline__ void cp16(uint32_t saddr, const void* g) {
    asm volatile("cp.async.cg.shared.global [%0], [%1], 16;" :: "r"(saddr), "l"(g));
}
__device__ __forceinline__ void cp_commit() { asm volatile("cp.async.commit_group;"); }
__device__ __forceinline__ void mma_f16(float c[4], const uint32_t a[4], const uint32_t b[2]) {
    asm volatile(
        "mma.sync.aligned.m16n8k16.row.col.f32.f16.f16.f32 "
        "{%0,%1,%2,%3}, {%4,%5,%6,%7}, {%8,%9}, {%0,%1,%2,%3};"
        : "+f"(c[0]), "+f"(c[1]), "+f"(c[2]), "+f"(c[3])
        : "r"(a[0]), "r"(a[1]), "r"(a[2]), "r"(a[3]), "r"(b[0]), "r"(b[1]));
}
__device__ __forceinline__ void ldsm_x4(uint32_t r[4], uint32_t saddr) {
    asm volatile("ldmatrix.sync.aligned.m8n8.x4.shared.b16 {%0,%1,%2,%3}, [%4];"
        : "=r"(r[0]), "=r"(r[1]), "=r"(r[2]), "=r"(r[3]) : "r"(saddr));
}
__device__ __forceinline__ void ldsm_x4t(uint32_t r[4], uint32_t saddr) {
    asm volatile("ldmatrix.sync.aligned.m8n8.x4.trans.shared.b16 {%0,%1,%2,%3}, [%4];"
        : "=r"(r[0]), "=r"(r[1]), "=r"(r[2]), "=r"(r[3]) : "r"(saddr));
}
__device__ __forceinline__ void ldsm_x2t(uint32_t r[2], uint32_t saddr) {
    asm volatile("ldmatrix.sync.aligned.m8n8.x2.trans.shared.b16 {%0,%1}, [%2];"
        : "=r"(r[0]), "=r"(r[1]) : "r"(saddr));
}
__device__ __forceinline__ uint32_t packh2(float a, float b) {
    __half2 h = __floats2half2_rn(a, b);
    return *(uint32_t*)&h;
}
__device__ __forceinline__ uint32_t ex2h2(uint32_t x) {
    uint32_t r; asm("ex2.approx.f16x2 %0, %1;" : "=r"(r) : "r"(x)); return r;
}

// ---------------- prep: fp32 -> fp16 ----------------
__global__ void tohalf_kernel(const float2* __restrict__ in, __half2* __restrict__ out, int n2) {
    int i = blockIdx.x * blockDim.x + threadIdx.x;
    if (i >= n2) return;
    float2 v = in[i];
    out[i] = __floats2half2_rn(v.x, v.y);
}

// ---------------- step 1: gather bias once -> [token][head] half ----------------
__global__ void bias16_kernel(const float* __restrict__ table,
                              const int*   __restrict__ ridx) {
    int t = blockIdx.x * blockDim.x + threadIdx.x;   // 0..65535
    if (t >= NTOK * NTOK) return;
    int r = ridx[t];
    __half hb[8];
    #pragma unroll
    for (int h = 0; h < NH; h++)
        hb[h] = __float2half_rn(table[r * NH + h] * LOG2E);
    *(uint4*)&g_biasb[t * NH] = *(uint4*)hb;
}

// ---------------- step 2: streaming combine: cmb = bias + mask*log2e ----------
__global__ void cmb_kernel(const float* __restrict__ mask) {
    int t = blockIdx.x * blockDim.x + threadIdx.x;   // 0..32767 (half2 units)
    int w = blockIdx.y;
    float2 mm = ((const float2*)mask)[((size_t)w << 15) + t];
    float mx = mm.x * LOG2E, my = mm.y * LOG2E;
    uint4 u0 = *(const uint4*)&g_biasb[(2 * t) * NH];
    uint4 u1 = *(const uint4*)&g_biasb[(2 * t + 1) * NH];
    const __half* b0 = (const __half*)&u0;
    const __half* b1 = (const __half*)&u1;
    __half2* c2 = (__half2*)g_cmb + ((size_t)(w * NH) << 15);
    #pragma unroll
    for (int h = 0; h < NH; h++) {
        float f0 = __half2float(b0[h]) + mx;
        float f1 = __half2float(b1[h]) + my;
        c2[((size_t)h << 15) + t] = __floats2half2_rn(f0, f1);
    }
}

// ---------------- fp16 NT GEMM, BK=64, ldmatrix fragments ----------------
#define GRB 144
#define GSTB (128 * GRB)
template<bool QKV_MODE>
__global__ __launch_bounds__(256, 2)
void gemm_f16(const __half* __restrict__ A, const __half* __restrict__ B,
              const float* __restrict__ bias, void* __restrict__ Cv,
              int M, int N, int K)
{
    extern __shared__ __half smh[];
    const uint32_t smem0 = (uint32_t)__cvta_generic_to_shared(smh);
    const uint32_t AsB = smem0;
    const uint32_t BsB = smem0 + 2 * GSTB;

    const int tid  = threadIdx.x;
    const int warp = tid >> 5, lane = tid & 31;
    const int qg   = lane >> 2, tg = lane & 3;
    const int wm   = (warp >> 2) * 64;
    const int wn   = (warp & 3) * 32;
    const int row0 = blockIdx.y * 128, col0 = blockIdx.x * 128;

    const uint32_t aoff = (uint32_t)((lane & 15) * GRB + (lane >> 4) * 16) + (uint32_t)(wm * GRB);
    const uint32_t boff = (uint32_t)(((lane & 7) + 8 * ((lane >> 4) & 1)) * GRB
                                     + ((lane >> 3) & 1) * 16) + (uint32_t)(wn * GRB);

    float c[4][4][4];
    #pragma unroll
    for (int i = 0; i < 4; i++)
        #pragma unroll
        for (int j = 0; j < 4; j++)
            #pragma unroll
            for (int t = 0; t < 4; t++) c[i][j][t] = 0.0f;

    const int KT = K / 64;

    auto load_stage = [&](int stage, int k0) {
        #pragma unroll
        for (int i = 0; i < 4; i++) {
            int id = tid + i * 256;
            int r = id >> 3, c8 = (id & 7) * 8;
            cp16(AsB + stage * GSTB + r * GRB + (id & 7) * 16,
                 A + (size_t)(row0 + r) * K + k0 + c8);
            cp16(BsB + stage * GSTB + r * GRB + (id & 7) * 16,
                 B + (size_t)(col0 + r) * K + k0 + c8);
        }
        cp_commit();
    };

    load_stage(0, 0);

    for (int kt = 0; kt < KT; kt++) {
        if (kt + 1 < KT) {
            load_stage((kt + 1) & 1, (kt + 1) * 64);
            asm volatile("cp.async.wait_group 1;");
        } else {
            asm volatile("cp.async.wait_group 0;");
        }
        __syncthreads();

        const uint32_t Asb = AsB + (kt & 1) * GSTB;
        const uint32_t Bsb = BsB + (kt & 1) * GSTB;

        #pragma unroll
        for (int ks = 0; ks < 4; ks++) {
            uint32_t af[4][4], bf[4][2];
            #pragma unroll
            for (int i = 0; i < 4; i++)
                ldsm_x4(af[i], Asb + aoff + i * 16 * GRB + ks * 32);
            #pragma unroll
            for (int jp = 0; jp < 2; jp++) {
                uint32_t bt[4];
                ldsm_x4(bt, Bsb + boff + jp * 16 * GRB + ks * 32);
                bf[2 * jp][0] = bt[0]; bf[2 * jp][1] = bt[1];
                bf[2 * jp + 1][0] = bt[2]; bf[2 * jp + 1][1] = bt[3];
            }
            #pragma unroll
            for (int i = 0; i < 4; i++)
                #pragma unroll
                for (int j = 0; j < 4; j++)
                    mma_f16(c[i][j], af[i], bf[j]);
        }
        __syncthreads();
    }

    const float qscale = (float)(0.17677669529663687 * 1.4426950408889634);
    #pragma unroll
    for (int i = 0; i < 4; i++) {
        int row = row0 + wm + i * 16 + qg;
        #pragma unroll
        for (int j = 0; j < 4; j++) {
            int col = col0 + wn + j * 8 + 2 * tg;
            float b0 = bias[col], b1 = bias[col + 1];
            float v00 = c[i][j][0] + b0, v01 = c[i][j][1] + b1;
            float v10 = c[i][j][2] + b0, v11 = c[i][j][3] + b1;
            if (QKV_MODE) {
                if (col < 256) { v00 *= qscale; v01 *= qscale; v10 *= qscale; v11 *= qscale; }
                __half* C = (__half*)Cv;
                *(__half2*)&C[(size_t)row * N + col]       = __floats2half2_rn(v00, v01);
                *(__half2*)&C[(size_t)(row + 8) * N + col] = __floats2half2_rn(v10, v11);
            } else {
                float* C = (float*)Cv;
                *(float2*)&C[(size_t)row * N + col]       = make_float2(v00, v01);
                *(float2*)&C[(size_t)(row + 8) * N + col] = make_float2(v10, v11);
            }
        }
    }
}

// ---------------- fp16 flash attention: f16x2 ex2 + ones-column row sums ------
#define ARB 80                   // row bytes for Q/K/V tiles (40 halfs)
__global__ __launch_bounds__(256, 2)
void attn_f16()
{
    extern __shared__ __half smh[];
    const uint32_t smem0 = (uint32_t)__cvta_generic_to_shared(smh);
    const uint32_t QsB = smem0;
    const uint32_t KsB = smem0 + 256 * ARB;
    const uint32_t VsB = smem0 + 2 * 256 * ARB;

    const int bh = blockIdx.x, b = bh >> 3, h = bh & 7;
    const int tid = threadIdx.x, warp = tid >> 5, lane = tid & 31;
    const int qg = lane >> 2, tg = lane & 3;

    const __half* base = g_qkv + (size_t)b * NTOK * QKVD + h * 32;

    #pragma unroll
    for (int i = 0; i < 4; i++) {
        int id = tid + i * 256;
        int m = id >> 2, cb = (id & 3) * 16;
        const __half* src = base + m * QKVD + (id & 3) * 8;
        cp16(QsB + m * ARB + cb, src);
        cp16(KsB + m * ARB + cb, src + 256);
        cp16(VsB + m * ARB + cb, src + 512);
    }
    cp_commit();

    // V ones-column: col 32 = 1.0, cols 33..39 = 0 (bytes 64..79 of each V row)
    *(uint4*)((char*)smh + 2 * 256 * ARB + tid * ARB + 64) = make_uint4(0x3C00u, 0u, 0u, 0u);

    asm volatile("cp.async.wait_group 0;");
    __syncthreads();

    const int wm = warp * 32;
    const __half2* cmb = (const __half2*)g_cmb + ((size_t)(((b & 63) * NH + h)) << 15);

    const uint32_t aoff = (uint32_t)((lane & 15) * ARB + (lane >> 4) * 16);
    const uint32_t koff = (uint32_t)(((lane & 7) + 8 * ((lane >> 4) & 1)) * ARB
                                     + ((lane >> 3) & 1) * 16);
    const uint32_t voff = aoff;
    const uint32_t v1off = (uint32_t)((lane & 15) * ARB + 64);   // ones-column tile

    uint32_t qf[2][2][4];
    #pragma unroll
    for (int i = 0; i < 2; i++)
        #pragma unroll
        for (int ks = 0; ks < 2; ks++)
            ldsm_x4(qf[i][ks], QsB + aoff + (wm + 16 * i) * ARB + ks * 32);

    float O[2][5][4];            // j=4 accumulates row sums (ones column)
    #pragma unroll
    for (int i = 0; i < 2; i++)
        #pragma unroll
        for (int j = 0; j < 5; j++)
            #pragma unroll
            for (int t = 0; t < 4; t++) O[i][j][t] = 0.0f;

    #pragma unroll 1
    for (int nb = 0; nb < 8; nb++) {
        const int n0 = nb * 32;

        // ---- S init from fused half table + shift
        float S[2][4][4];
        #pragma unroll
        for (int i = 0; i < 2; i++) {
            int row = wm + 16 * i + qg;
            #pragma unroll
            for (int j = 0; j < 4; j++) {
                int ci = (n0 >> 1) + 4 * j + tg;
                float2 v0 = __half22float2(cmb[row * 128 + ci]);
                float2 v1 = __half22float2(cmb[(row + 8) * 128 + ci]);
                S[i][j][0] = v0.x + SHIFT;
                S[i][j][1] = v0.y + SHIFT;
                S[i][j][2] = v1.x + SHIFT;
                S[i][j][3] = v1.y + SHIFT;
            }
        }

        // ---- K fragments
        uint32_t kf[2][4][2];
        #pragma unroll
        for (int ks = 0; ks < 2; ks++)
            #pragma unroll
            for (int jp = 0; jp < 2; jp++) {
                uint32_t t4[4];
                ldsm_x4(t4, KsB + koff + (n0 + 16 * jp) * ARB + ks * 32);
                kf[ks][2 * jp][0] = t4[0]; kf[ks][2 * jp][1] = t4[1];
                kf[ks][2 * jp + 1][0] = t4[2]; kf[ks][2 * jp + 1][1] = t4[3];
            }

        // ---- S += Q K^T
        #pragma unroll
        for (int ks = 0; ks < 2; ks++)
            #pragma unroll
            for (int j = 0; j < 4; j++) {
                mma_f16(S[0][j], qf[0][ks], kf[ks][j]);
                mma_f16(S[1][j], qf[1][ks], kf[ks][j]);
            }

        // ---- softmax: p = 2^S via f16x2 MUFU, straight into A-fragments
        uint32_t ph[2][2][4];
        #pragma unroll
        for (int i = 0; i < 2; i++)
            #pragma unroll
            for (int ks2 = 0; ks2 < 2; ks2++) {
                ph[i][ks2][0] = ex2h2(packh2(S[i][2 * ks2][0],     S[i][2 * ks2][1]));
                ph[i][ks2][1] = ex2h2(packh2(S[i][2 * ks2][2],     S[i][2 * ks2][3]));
                ph[i][ks2][2] = ex2h2(packh2(S[i][2 * ks2 + 1][0], S[i][2 * ks2 + 1][1]));
                ph[i][ks2][3] = ex2h2(packh2(S[i][2 * ks2 + 1][2], S[i][2 * ks2 + 1][3]));
            }

        // ---- V fragments (cols 0..31) + ones-column tile (cols 32..39)
        uint32_t vf[2][4][2], vf1[2][2];
        #pragma unroll
        for (int ks2 = 0; ks2 < 2; ks2++) {
            #pragma unroll
            for (int jp = 0; jp < 2; jp++) {
                uint32_t t4[4];
                ldsm_x4t(t4, VsB + voff + (n0 + 16 * ks2) * ARB + jp * 32);
                vf[ks2][2 * jp][0] = t4[0]; vf[ks2][2 * jp][1] = t4[1];
                vf[ks2][2 * jp + 1][0] = t4[2]; vf[ks2][2 * jp + 1][1] = t4[3];
            }
            ldsm_x2t(vf1[ks2], VsB + v1off + (n0 + 16 * ks2) * ARB);
        }

        // ---- O += P V  (plus row-sum column)
        #pragma unroll
        for (int ks2 = 0; ks2 < 2; ks2++) {
            #pragma unroll
            for (int j = 0; j < 4; j++) {
                mma_f16(O[0][j], ph[0][ks2], vf[ks2][j]);
                mma_f16(O[1][j], ph[1][ks2], vf[ks2][j]);
            }
            mma_f16(O[0][4], ph[0][ks2], vf1[ks2]);
            mma_f16(O[1][4], ph[1][ks2], vf1[ks2]);
        }
    }

    // ---- epilogue: row sums live in lanes tg=0 (col 32); broadcast + normalize
    #pragma unroll
    for (int i = 0; i < 2; i++) {
        float s0 = __shfl_sync(0xffffffffu, O[i][4][0], lane & 28);
        float s1 = __shfl_sync(0xffffffffu, O[i][4][2], lane & 28);
        float inv0 = 1.0f / s0, inv1 = 1.0f / s1;
        int row = wm + 16 * i + qg;
        #pragma unroll
        for (int j = 0; j < 4; j++) {
            int col = h * 32 + 8 * j + 2 * tg;
            *(__half2*)&g_att[((size_t)b * NTOK + row) * CDIM + col] =
                __floats2half2_rn(O[i][j][0] * inv0, O[i][j][1] * inv0);
            *(__half2*)&g_att[((size_t)b * NTOK + row + 8) * CDIM + col] =
                __floats2half2_rn(O[i][j][2] * inv1, O[i][j][3] * inv1);
        }
    }
}

// --------------------------------------------------------------------------
extern "C" void kernel_launch(void* const* d_in, const int* in_sizes, int n_in,
                              void* d_out, int out_size)
{
    const float* x      = (const float*)d_in[0];
    const float* mask   = (const float*)d_in[1];
    const float* qkv_w  = (const float*)d_in[2];
    const float* qkv_b  = (const float*)d_in[3];
    const float* proj_w = (const float*)d_in[4];
    const float* proj_b = (const float*)d_in[5];
    const float* table  = (const float*)d_in[6];
    const int*   ridx   = (const int*)d_in[7];
    float* out = (float*)d_out;

    __half *qkv_ptr, *att_ptr, *xh_ptr, *wh_ptr;
    cudaGetSymbolAddress((void**)&qkv_ptr, g_qkv);
    cudaGetSymbolAddress((void**)&att_ptr, g_att);
    cudaGetSymbolAddress((void**)&xh_ptr,  g_xh);
    cudaGetSymbolAddress((void**)&wh_ptr,  g_wh);
    __half* qkvw_h  = wh_ptr;
    __half* projw_h = wh_ptr + QKVD * CDIM;

    const int gemm_smem = 4 * GSTB;           // 73728 B
    const int attn_smem = 3 * 256 * ARB;      // 61440 B
    cudaFuncSetAttribute((const void*)gemm_f16<true>,
                         cudaFuncAttributeMaxDynamicSharedMemorySize, gemm_smem);
    cudaFuncSetAttribute((const void*)gemm_f16<false>,
                         cudaFuncAttributeMaxDynamicSharedMemorySize, gemm_smem);
    cudaFuncSetAttribute((const void*)attn_f16,
                         cudaFuncAttributeMaxDynamicSharedMemorySize, attn_smem);

    // 0) prep
    tohalf_kernel<<<(NBATCH * NTOK * CDIM / 2 + 255) / 256, 256>>>(
        (const float2*)x, (__half2*)xh_ptr, NBATCH * NTOK * CDIM / 2);
    tohalf_kernel<<<(QKVD * CDIM / 2 + 255) / 256, 256>>>(
        (const float2*)qkv_w, (__half2*)qkvw_h, QKVD * CDIM / 2);
    tohalf_kernel<<<(CDIM * CDIM / 2 + 255) / 256, 256>>>(
        (const float2*)proj_w, (__half2*)projw_h, CDIM * CDIM / 2);
    bias16_kernel<<<NTOK * NTOK / 256, 256>>>(table, ridx);
    cmb_kernel<<<dim3(128, 64), 256>>>(mask);

    // 2) QKV projection -> fp16 (Q pre-scaled by scale*log2e)
    gemm_f16<true><<<dim3(QKVD / 128, (NBATCH * NTOK) / 128), 256, gemm_smem>>>(
        xh_ptr, qkvw_h, qkv_b, qkv_ptr, NBATCH * NTOK, QKVD, CDIM);

    // 3) window attention
    attn_f16<<<NBATCH * NH, 256, attn_smem>>>();

    // 4) output projection -> fp32 d_out
    gemm_f16<false><<<dim3(CDIM / 128, (NBATCH * NTOK) / 128), 256, gemm_smem>>>(
        att_ptr, projw_h, proj_b, out, NBATCH * NTOK, CDIM, CDIM);
}